// round 14
// baseline (speedup 1.0000x reference)
#include <cuda_runtime.h>
#include <cstdint>

#define NB 128
#define CIN 256
#define HH 28
#define WW 28
#define HWPIX 784
#define PPOS 900        // 30x30 padded positions
#define TAPS 9
#define CW 8            // 256 ch / 32 bits

// scratch — zero-initialized at module load; border of g_xpack is never written,
// so it stays zero across all calls (interior rewritten every call).
__device__ __align__(16) uint32_t g_xpack[(size_t)NB * PPOS * CW];   // [n][pos][word]
__device__ __align__(16) uint32_t g_wpack[CIN * TAPS * CW];          // [co][tap][word]
__device__ float g_scale2[CIN];            // -2 * gamma/sqrt(var+eps)
__device__ float g_bias2[9 * CIN];         // per boundary-class fused bias

// ---------------- merged prep ----------------
// grid = NB*HH (pack_x role, 224 threads used) + CIN (pack_w+BN role, 72 threads used)
#define PACKX_BLOCKS (NB * HH)
__global__ __launch_bounds__(224)
void prep_kernel(const float* __restrict__ x, const float* __restrict__ w,
                 const float* __restrict__ gamma, const float* __restrict__ beta,
                 const float* __restrict__ mean, const float* __restrict__ var) {
    int b = blockIdx.x;
    if (b < PACKX_BLOCKS) {
        // ---- pack_x role ----
        int n = b / HH, hh = b % HH;
        int word = threadIdx.x / 28, ww = threadIdx.x % 28;
        const float* xp = x + ((size_t)(n * CIN + word * 32) * HH + hh) * WW + ww;
        uint32_t bits = 0;
#pragma unroll
        for (int i = 0; i < 32; i++) {
            float v = xp[(size_t)i * HWPIX];
            bits |= (v < 0.f ? 1u : 0u) << i;
        }
        g_xpack[((size_t)n * PPOS + (hh + 1) * 30 + (ww + 1)) * CW + word] = bits;
        return;
    }
    // ---- pack_w + BN role ----
    __shared__ int s_pc[72];
    __shared__ int s_negw[TAPS];
    int co = b - PACKX_BLOCKS;
    int tid = threadIdx.x;
    if (tid < 72) {
        int tap = tid / 8, word = tid % 8;
        uint32_t bits = 0;
#pragma unroll
        for (int i = 0; i < 32; i++) {
            float v = w[((size_t)(co * CIN + word * 32 + i)) * TAPS + tap];
            bits |= (v < 0.f ? 1u : 0u) << i;
        }
        g_wpack[(co * TAPS + tap) * CW + word] = bits;
        s_pc[tid] = __popc(bits);
    }
    __syncthreads();
    if (tid < TAPS) {
        int s = 0;
#pragma unroll
        for (int wd = 0; wd < CW; wd++) s += s_pc[tid * 8 + wd];
        s_negw[tid] = s;
    }
    __syncthreads();
    if (tid < 9) {   // tid = boundary class hv*3+wv
        int hv = tid / 3, wv = tid % 3;
        float inv = gamma[co] * rsqrtf(var[co] + 1e-5f);
        float bias = beta[co] - mean[co] * inv;
        int nv = 0, s = 0;
#pragma unroll
        for (int kh = 0; kh < 3; kh++) {
#pragma unroll
            for (int kw = 0; kw < 3; kw++) {
                bool inval = (hv == 0 && kh == 0) || (hv == 2 && kh == 2) ||
                             (wv == 0 && kw == 0) || (wv == 2 && kw == 2);
                if (inval) s += s_negw[kh * 3 + kw];
                else nv++;
            }
        }
        float convBase = 256.f * nv + 2.f * (float)s;
        g_bias2[tid * CIN + co] = convBase * inv + bias;
        if (tid == 0) g_scale2[co] = -2.f * inv;
    }
}

// full adder (3:2 compressor): 2 LOP3
__device__ __forceinline__ void fa(uint32_t a, uint32_t b, uint32_t c,
                                   uint32_t& s, uint32_t& cy) {
    s = a ^ b ^ c;
    cy = (a & b) | (c & (a | b));
}

// 6-word popcount, 1 FA + 5 POPC (keeps measured optimum ratio: 1 FA / 4 words)
__device__ __forceinline__ int popc6(uint32_t e0, uint32_t e1, uint32_t e2,
                                     uint32_t e3, uint32_t e4, uint32_t e5) {
    uint32_t s, c;
    fa(e0, e1, e2, s, c);
    int w1 = __popc(s) + __popc(e3) + __popc(e4) + __popc(e5);
    return w1 + 2 * __popc(c);
}

// ---------------- main conv ----------------
// grid (NB, 16 co-groups of 16, 2 row-halves), block 224 = 4 cog4 x 56 pixel-threads
// thread: 7 pixels (quarter row) x 4 co (2 packed pairs); block covers 14 rows x 16 co
// Channel dim processed in 4 uint2 quarters to shrink the live register set -> occ 4.
#define XROWS 16   // 14 output rows + 2 halo
__global__ __launch_bounds__(224, 4)
void popc_conv_kernel(const float* __restrict__ x, float* __restrict__ out) {
    __shared__ uint32_t s_x[XROWS * 30 * CW];   // 15360 B
    __shared__ uint32_t s_w[16 * TAPS * CW];    // 4608 B
    int tid = threadIdx.x;
    int n = blockIdx.x, cg16 = blockIdx.y, rh = blockIdx.z;

    {
        const uint4* xs = (const uint4*)(g_xpack + ((size_t)n * PPOS + rh * 14 * 30) * CW);
        uint4* xd = (uint4*)s_x;
        for (int i = tid; i < XROWS * 30 * CW / 4; i += 224) xd[i] = xs[i];
        const uint4* ws = (const uint4*)(g_wpack + (size_t)cg16 * 16 * TAPS * CW);
        uint4* wd = (uint4*)s_w;
        for (int i = tid; i < 16 * TAPS * CW / 4; i += 224) wd[i] = ws[i];
    }
    __syncthreads();

    int cog4 = tid / 56, q = tid % 56;
    int hl = q >> 2, w0 = 7 * (q & 3);
    int h = rh * 14 + hl;

    int acc[7][2];   // [pixel][co-pair], lo16 = even co, hi16 = odd co
#pragma unroll
    for (int p = 0; p < 7; p++) {
        acc[p][0] = 0; acc[p][1] = 0;
    }

#pragma unroll 1
    for (int kh = 0; kh < 3; kh++) {
#pragma unroll 1
        for (int qv = 0; qv < 4; qv++) {   // channel quarter: 2 words (64 ch)
            uint2 xq[9];
            int xbase = ((hl + kh) * 30 + w0) * CW + qv * 2;
#pragma unroll
            for (int i = 0; i < 9; i++)
                xq[i] = *(const uint2*)&s_x[xbase + i * CW];
#pragma unroll
            for (int cp = 0; cp < 2; cp++) {
                uint2 wqa[3], wqb[3];
                int wbase = ((cog4 * 4 + cp * 2) * TAPS + kh * 3) * CW + qv * 2;
#pragma unroll
                for (int kw = 0; kw < 3; kw++) {
                    wqa[kw] = *(const uint2*)&s_w[wbase + kw * CW];
                    wqb[kw] = *(const uint2*)&s_w[wbase + TAPS * CW + kw * CW];
                }
#pragma unroll
                for (int p = 0; p < 7; p++) {
                    uint2 x0 = xq[p], x1 = xq[p + 1], x2 = xq[p + 2];
                    int ta = popc6(x0.x ^ wqa[0].x, x0.y ^ wqa[0].y,
                                   x1.x ^ wqa[1].x, x1.y ^ wqa[1].y,
                                   x2.x ^ wqa[2].x, x2.y ^ wqa[2].y);
                    int tb = popc6(x0.x ^ wqb[0].x, x0.y ^ wqb[0].y,
                                   x1.x ^ wqb[1].x, x1.y ^ wqb[1].y,
                                   x2.x ^ wqb[2].x, x2.y ^ wqb[2].y);
                    acc[p][cp] += ta + tb * 65536;   // IMAD -> fma pipe
                }
            }
        }
    }

    // epilogue: fused BN (+ boundary correction) + hardtanh + residual
    int hv = (h == 0) ? 0 : (h == 27 ? 2 : 1);
    int co_base = cg16 * 16 + cog4 * 4;
#pragma unroll
    for (int p = 0; p < 7; p++) {
        int w = w0 + p;
        int wvc = (w == 0) ? 0 : (w == 27 ? 2 : 1);
        int cls = hv * 3 + wvc;
#pragma unroll
        for (int cp = 0; cp < 2; cp++) {
            int ca = acc[p][cp] & 0xFFFF;
            int cb = acc[p][cp] >> 16;
            int co = co_base + cp * 2;
            float s2a = __ldg(g_scale2 + co), s2b = __ldg(g_scale2 + co + 1);
            float b2a = __ldg(g_bias2 + cls * CIN + co);
            float b2b = __ldg(g_bias2 + cls * CIN + co + 1);
            float va = fminf(fmaxf(fmaf((float)ca, s2a, b2a), -1.f), 1.f);
            float vb = fminf(fmaxf(fmaf((float)cb, s2b, b2b), -1.f), 1.f);
            size_t idx = ((size_t)(n * CIN + co)) * HWPIX + h * WW + w;
            out[idx] = va + x[idx];
            out[idx + HWPIX] = vb + x[idx + HWPIX];
        }
    }
}

// ---------------- launch ----------------
extern "C" void kernel_launch(void* const* d_in, const int* in_sizes, int n_in,
                              void* d_out, int out_size) {
    const float* x     = (const float*)d_in[0];
    const float* w     = (const float*)d_in[1];
    const float* gamma = (const float*)d_in[2];
    const float* beta  = (const float*)d_in[3];
    const float* rmean = (const float*)d_in[4];
    const float* rvar  = (const float*)d_in[5];
    float* out = (float*)d_out;

    prep_kernel<<<PACKX_BLOCKS + CIN, 224>>>(x, w, gamma, beta, rmean, rvar); // launch 0
    popc_conv_kernel<<<dim3(NB, 16, 2), 224>>>(x, out);                       // launch 1
}